// round 10
// baseline (speedup 1.0000x reference)
#include <cuda_runtime.h>
#include <math.h>

// Problem constants (fixed-shape problem)
#define NTOK  8192
#define DDIM  1024
#define EEXP  64
#define RRANK 64
#define GGRP  8
#define MLOC  8

#define TILE_T 32           // tokens per expert tile
#define MAX_TILES 512       // per slot: <= N/TILE_T + E = 320

// ---------------- scratch (device globals; no allocations) ----------------
__device__ int   g_eid[NTOK * 2];      // global expert id per (token, slot)
__device__ float g_gate2[NTOK * 2];    // gate per (token, slot)
__device__ int   g_cnt[2][EEXP];
__device__ int   g_off[2][EEXP];
__device__ int   g_fill[2][EEXP];
__device__ int   g_tok[2][NTOK];       // token index, grouped by expert, per slot
__device__ float g_tg[2][NTOK];        // matching gate
__device__ int   g_tiles[2][MAX_TILES];// packed: (e<<16) | tile_index_within_expert
__device__ int   g_ntiles[2];
__device__ float g_extra[NTOK * DDIM]; // slot-1 partial output (merged by add_kernel)

// ---------------- init: zero counters ----------------
__global__ void init_kernel() {
    int t = threadIdx.x;
    if (t < EEXP) {
        g_cnt[0][t] = 0; g_cnt[1][t] = 0;
        g_fill[0][t] = 0; g_fill[1][t] = 0;
    }
    if (t == 0) { g_ntiles[0] = 0; g_ntiles[1] = 0; }
}

// ---------------- routing: one warp per token (unchanged, verified) ----------------
__global__ void routing_kernel(const float* __restrict__ h,
                               const float* __restrict__ Wg,
                               const float* __restrict__ bg,
                               const float* __restrict__ Wloc,
                               float* __restrict__ o_eid,    // may be null
                               float* __restrict__ o_gate,   // may be null
                               float* __restrict__ o_grp,    // may be null
                               int n)
{
    int warp = (blockIdx.x * blockDim.x + threadIdx.x) >> 5;
    int lane = threadIdx.x & 31;
    if (warp >= n) return;

    const float* hrow = h + (size_t)warp * DDIM;

    float hv[32];
#pragma unroll
    for (int i = 0; i < 32; i++) hv[i] = hrow[i * 32 + lane];

    // ---- stage 1: group scores (G=8) ----
    float sg[GGRP];
#pragma unroll
    for (int g = 0; g < GGRP; g++) sg[g] = 0.f;
#pragma unroll
    for (int i = 0; i < 32; i++) {
        int d = i * 32 + lane;
        const float4* wp = (const float4*)(Wg + (size_t)d * GGRP);
        float4 wa = wp[0], wb = wp[1];
        float x = hv[i];
        sg[0] += x * wa.x; sg[1] += x * wa.y; sg[2] += x * wa.z; sg[3] += x * wa.w;
        sg[4] += x * wb.x; sg[5] += x * wb.y; sg[6] += x * wb.z; sg[7] += x * wb.w;
    }
#pragma unroll
    for (int g = 0; g < GGRP; g++) {
#pragma unroll
        for (int off = 16; off > 0; off >>= 1)
            sg[g] += __shfl_xor_sync(0xFFFFFFFFu, sg[g], off);
        sg[g] += bg[g];
    }
    int gi = 0; float best = sg[0];
#pragma unroll
    for (int g = 1; g < GGRP; g++) if (sg[g] > best) { best = sg[g]; gi = g; }

    // ---- stage 2: local scores for selected group (M=8) ----
    float sl[MLOC];
#pragma unroll
    for (int m = 0; m < MLOC; m++) sl[m] = 0.f;
    const float* wl = Wloc + (size_t)gi * DDIM * MLOC;
#pragma unroll
    for (int i = 0; i < 32; i++) {
        int d = i * 32 + lane;
        const float4* wp = (const float4*)(wl + (size_t)d * MLOC);
        float4 wa = wp[0], wb = wp[1];
        float x = hv[i];
        sl[0] += x * wa.x; sl[1] += x * wa.y; sl[2] += x * wa.z; sl[3] += x * wa.w;
        sl[4] += x * wb.x; sl[5] += x * wb.y; sl[6] += x * wb.z; sl[7] += x * wb.w;
    }
#pragma unroll
    for (int m = 0; m < MLOC; m++) {
#pragma unroll
        for (int off = 16; off > 0; off >>= 1)
            sl[m] += __shfl_xor_sync(0xFFFFFFFFu, sl[m], off);
    }
    int m1 = 0; float v1 = sl[0];
#pragma unroll
    for (int m = 1; m < MLOC; m++) if (sl[m] > v1) { v1 = sl[m]; m1 = m; }
    int m2 = -1; float v2 = -INFINITY;
#pragma unroll
    for (int m = 0; m < MLOC; m++) if (m != m1 && sl[m] > v2) { v2 = sl[m]; m2 = m; }

    float e2 = expf(v2 - v1);
    float inv = 1.0f / (1.0f + e2);
    float gate0 = inv;
    float gate1 = e2 * inv;

    int eid0 = gi * MLOC + m1;
    int eid1 = gi * MLOC + m2;

    if (lane == 0) {
        g_eid[2 * warp + 0] = eid0;
        g_eid[2 * warp + 1] = eid1;
        g_gate2[2 * warp + 0] = gate0;
        g_gate2[2 * warp + 1] = gate1;
        atomicAdd(&g_cnt[0][eid0], 1);
        atomicAdd(&g_cnt[1][eid1], 1);
        if (o_eid)  { o_eid[2 * warp + 0] = (float)eid0; o_eid[2 * warp + 1] = (float)eid1; }
        if (o_gate) { o_gate[2 * warp + 0] = gate0;      o_gate[2 * warp + 1] = gate1; }
        if (o_grp)  { o_grp[warp] = (float)gi; }
    }
}

// ---------------- prefix sums + tile lists (tiny; single thread) ----------------
__global__ void prefix_kernel() {
    if (threadIdx.x != 0 || blockIdx.x != 0) return;
#pragma unroll
    for (int s = 0; s < 2; s++) {
        int acc = 0, nt = 0;
        for (int e = 0; e < EEXP; e++) {
            g_off[s][e] = acc;
            int c = g_cnt[s][e];
            acc += c;
            int t = (c + TILE_T - 1) / TILE_T;
            for (int i = 0; i < t && nt < MAX_TILES; i++)
                g_tiles[s][nt++] = (e << 16) | i;
        }
        g_ntiles[s] = nt;
    }
}

// ---------------- scatter tokens into per-expert, per-slot buckets ----------------
__global__ void scatter_kernel(int n) {
    int t = blockIdx.x * blockDim.x + threadIdx.x;
    if (t >= n) return;
#pragma unroll
    for (int j = 0; j < 2; j++) {
        int e = g_eid[2 * t + j];
        int p = g_off[j][e] + atomicAdd(&g_fill[j][e], 1);
        g_tok[j][p] = t;
        g_tg[j][p]  = g_gate2[2 * t + j];
    }
}

// ---------------- packed-f32x2 helpers ----------------
#define FFMA2(d, a, b) asm("fma.rn.f32x2 %0, %1, %2, %0;" : "+l"(d) : "l"(a), "l"(b))

__device__ __forceinline__ float lo32(unsigned long long v) {
    return __uint_as_float((unsigned int)v);
}
__device__ __forceinline__ float hi32(unsigned long long v) {
    return __uint_as_float((unsigned int)(v >> 32));
}

// ---------------- expert compute: one tile = (slot, expert, 32 tokens) ----------------
// Combined kernel for BOTH slots (slot0 -> out, slot1 -> g_extra); no atomics.
// Phase 1: A = gate * relu(H @ W1[e])   (32 x 64)   token-pair packed FFMA2
// Phase 2: O = A @ W2[e]                (32 x 1024) column-pair packed FFMA2
// Thread map: tg = tid&7 -> 4 tokens {4tg..4tg+3}; cg = tid>>3 -> 4 cols {4cg..4cg+3}.
__global__ void __launch_bounds__(128)
expert_kernel(const float* __restrict__ h,
              const float* __restrict__ W1,
              const float* __restrict__ W2,
              float* __restrict__ out)
{
    // Phase1: s_hs = H^T (k-major, tokens contiguous), s_wd = W1 chunk w/ cols duplicated
    // Phase2: s_as = A^T (r-major, tokens duplicated), s_wd reused plain 64x64 for W2
    __shared__ __align__(16) float s_hs[32 * 36];    //  4608 B
    __shared__ __align__(16) float s_wd[32 * 132];   // 16896 B (>= 64*64 plain)
    __shared__ __align__(16) float s_as[64 * 68];    // 17408 B
    __shared__ int   tok_s[TILE_T];
    __shared__ float gsc[TILE_T];

    int tid = threadIdx.x;
    int tg = tid & 7;        // token group: tokens 4tg..4tg+3
    int cg = tid >> 3;       // col group: cols 4cg..4cg+3 (0..15)

    int nt0 = g_ntiles[0];
    int ntt = nt0 + g_ntiles[1];

    for (int tile = blockIdx.x; tile < ntt; tile += gridDim.x) {
        int slot = (tile >= nt0) ? 1 : 0;
        int tloc = slot ? tile - nt0 : tile;
        int desc = g_tiles[slot][tloc];
        int e  = desc >> 16;
        int ti = desc & 0xFFFF;
        int cnt_e = g_cnt[slot][e];
        int base  = g_off[slot][e] + ti * TILE_T;
        int nv = cnt_e - ti * TILE_T;
        if (nv > TILE_T) nv = TILE_T;

        if (tid < TILE_T) {
            int rr = tid < nv ? tid : (nv - 1);   // clamp; invalid rows masked at store
            tok_s[tid] = g_tok[slot][base + rr];
            gsc[tid]   = g_tg[slot][base + rr];
        }
        __syncthreads();

        // ---------------- phase 1: A = gate * relu(H @ W1[e]) ----------------
        // acc[p][c]: p = token pair (tokens 4tg+2p, 4tg+2p+1), c = col 4cg+c
        unsigned long long acc[2][4];
#pragma unroll
        for (int p = 0; p < 2; p++)
#pragma unroll
            for (int c = 0; c < 4; c++) acc[p][c] = 0ull;

        const float* W1e = W1 + (size_t)e * DDIM * RRANK;

        for (int kc = 0; kc < DDIM / 32; kc++) {
            int k0 = kc * 32;
            // H^T fill: 32k x 32t (tokens contiguous, stride 36)
#pragma unroll
            for (int i = 0; i < 8; i++) {
                int lin = tid + i * 128;
                int t = lin >> 5, k = lin & 31;
                s_hs[k * 36 + t] = h[(size_t)tok_s[t] * DDIM + k0 + k];
            }
            // W1 chunk fill, each weight duplicated: s_wd[k][2c] = s_wd[k][2c+1] = w
#pragma unroll
            for (int i = 0; i < 16; i++) {
                int lin = tid + i * 128;
                int r = lin >> 6, c = lin & 63;
                float w = W1e[(size_t)(k0 + r) * RRANK + c];
                *(float2*)&s_wd[r * 132 + 2 * c] = make_float2(w, w);
            }
            __syncthreads();
#pragma unroll
            for (int kk = 0; kk < 32; kk++) {
                ulonglong2 hp = *(const ulonglong2*)&s_hs[kk * 36 + 4 * tg]; // (h0,h1),(h2,h3)
                ulonglong2 wA = *(const ulonglong2*)&s_wd[kk * 132 + 8 * cg];     // (w0,w0),(w1,w1)
                ulonglong2 wB = *(const ulonglong2*)&s_wd[kk * 132 + 8 * cg + 4]; // (w2,w2),(w3,w3)
                FFMA2(acc[0][0], hp.x, wA.x); FFMA2(acc[0][1], hp.x, wA.y);
                FFMA2(acc[0][2], hp.x, wB.x); FFMA2(acc[0][3], hp.x, wB.y);
                FFMA2(acc[1][0], hp.y, wA.x); FFMA2(acc[1][1], hp.y, wA.y);
                FFMA2(acc[1][2], hp.y, wB.x); FFMA2(acc[1][3], hp.y, wB.y);
            }
            __syncthreads();
        }

        // relu * gate -> A^T duplicated: s_as[r][2t] = s_as[r][2t+1] = a
#pragma unroll
        for (int p = 0; p < 2; p++) {
            int tA = 4 * tg + 2 * p, tB = tA + 1;
            float gA = gsc[tA], gB = gsc[tB];
#pragma unroll
            for (int c = 0; c < 4; c++) {
                int r = 4 * cg + c;
                float a = fmaxf(lo32(acc[p][c]), 0.f) * gA;
                float b = fmaxf(hi32(acc[p][c]), 0.f) * gB;
                *(float2*)&s_as[r * 68 + 2 * tA] = make_float2(a, a);
                *(float2*)&s_as[r * 68 + 2 * tB] = make_float2(b, b);
            }
        }
        // visibility of s_as ensured by the sync after the first W2 fill below

        // ---------------- phase 2: O = A @ W2[e] ----------------
        const float* W2e = W2 + (size_t)e * RRANK * DDIM;
        float* dst = slot ? g_extra : out;

        for (int ct = 0; ct < 16; ct++) {
            int c0 = ct * 64;
            // W2 col-tile fill: 64r x 64c plain (reuse s_wd)
#pragma unroll
            for (int i = 0; i < 32; i++) {
                int lin = tid + i * 128;
                int r = lin >> 6, c = lin & 63;
                s_wd[lin] = W2e[(size_t)r * DDIM + c0 + c];
            }
            __syncthreads();

            // oa[t][q]: t = token 4tg+t, q = col pair (4cg+2q, 4cg+2q+1)
            unsigned long long oa[4][2];
#pragma unroll
            for (int t = 0; t < 4; t++) { oa[t][0] = 0ull; oa[t][1] = 0ull; }
#pragma unroll
            for (int r = 0; r < RRANK; r++) {
                ulonglong2 a01 = *(const ulonglong2*)&s_as[r * 68 + 8 * tg];     // (a0,a0),(a1,a1)
                ulonglong2 a23 = *(const ulonglong2*)&s_as[r * 68 + 8 * tg + 4]; // (a2,a2),(a3,a3)
                ulonglong2 wp  = *(const ulonglong2*)&s_wd[r * 64 + 4 * cg];     // (w0,w1),(w2,w3)
                FFMA2(oa[0][0], a01.x, wp.x); FFMA2(oa[0][1], a01.x, wp.y);
                FFMA2(oa[1][0], a01.y, wp.x); FFMA2(oa[1][1], a01.y, wp.y);
                FFMA2(oa[2][0], a23.x, wp.x); FFMA2(oa[2][1], a23.x, wp.y);
                FFMA2(oa[3][0], a23.y, wp.x); FFMA2(oa[3][1], a23.y, wp.y);
            }
#pragma unroll
            for (int t = 0; t < 4; t++) {
                int tt = 4 * tg + t;
                if (tt < nv) {
                    float4 o;
                    o.x = lo32(oa[t][0]); o.y = hi32(oa[t][0]);
                    o.z = lo32(oa[t][1]); o.w = hi32(oa[t][1]);
                    *(float4*)&dst[(size_t)tok_s[tt] * DDIM + c0 + 4 * cg] = o;
                }
            }
            __syncthreads();   // protects s_wd refill next ct and s_as/tok_s reuse next tile
        }
    }
}

// ---------------- merge: out += g_extra ----------------
__global__ void add_kernel(float* __restrict__ out, int n4) {
    int i = blockIdx.x * blockDim.x + threadIdx.x;
    int stride = gridDim.x * blockDim.x;
    const float4* ex = (const float4*)g_extra;
    float4* o = (float4*)out;
    for (; i < n4; i += stride) {
        float4 a = o[i], b = ex[i];
        a.x += b.x; a.y += b.y; a.z += b.z; a.w += b.w;
        o[i] = a;
    }
}

// ---------------- launch ----------------
extern "C" void kernel_launch(void* const* d_in, const int* in_sizes, int n_in,
                              void* d_out, int out_size)
{
    const float* h    = (const float*)d_in[0];
    const float* Wg   = (const float*)d_in[1];
    const float* bg   = (const float*)d_in[2];
    const float* Wloc = (const float*)d_in[3];
    const float* W1   = (const float*)d_in[4];
    const float* W2   = (const float*)d_in[5];

    int n = in_sizes[0] / DDIM;                 // 8192
    if (n > NTOK) n = NTOK;

    float* out = (float*)d_out;

    // Optional concatenated tail outputs: out(N*D), expert_ids(2N), gate(2N), group_idx(N)
    size_t need = (size_t)n * DDIM + 5 * (size_t)n;
    float* o_eid  = nullptr;
    float* o_gate = nullptr;
    float* o_grp  = nullptr;
    if ((size_t)out_size >= need) {
        o_eid  = out + (size_t)n * DDIM;
        o_gate = o_eid + 2 * (size_t)n;
        o_grp  = o_gate + 2 * (size_t)n;
    }

    init_kernel<<<1, 128>>>();
    routing_kernel<<<(n + 7) / 8, 256>>>(h, Wg, bg, Wloc, o_eid, o_gate, o_grp, n);
    prefix_kernel<<<1, 32>>>();
    scatter_kernel<<<(n + 255) / 256, 256>>>(n);
    // Both slots in one wave: slot0 tiles write `out`, slot1 tiles write g_extra
    expert_kernel<<<592, 128>>>(h, W1, W2, out);
    // out += g_extra
    add_kernel<<<1024, 256>>>(out, n * DDIM / 4);
}

// round 11
// speedup vs baseline: 1.4169x; 1.4169x over previous
#include <cuda_runtime.h>
#include <math.h>

// Problem constants (fixed-shape problem)
#define NTOK  8192
#define DDIM  1024
#define EEXP  64
#define RRANK 64
#define GGRP  8
#define MLOC  8

#define TILE_T 32           // tokens per expert tile
#define MAX_TILES 512       // per slot: <= N/TILE_T + E = 320

// ---------------- scratch (device globals; no allocations) ----------------
__device__ int   g_eid[NTOK * 2];      // global expert id per (token, slot)
__device__ float g_gate2[NTOK * 2];    // gate per (token, slot)
__device__ int   g_cnt[2][EEXP];
__device__ int   g_off[2][EEXP];
__device__ int   g_fill[2][EEXP];
__device__ int   g_tok[2][NTOK];       // token index, grouped by expert, per slot
__device__ float g_tg[2][NTOK];        // matching gate
__device__ int   g_tiles[2][MAX_TILES];// packed: (e<<16) | tile_index_within_expert
__device__ int   g_ntiles[2];
__device__ float g_extra[NTOK * DDIM]; // slot-1 partial output (merged by add_kernel)

// ---------------- init: zero counters ----------------
__global__ void init_kernel() {
    int t = threadIdx.x;
    if (t < EEXP) {
        g_cnt[0][t] = 0; g_cnt[1][t] = 0;
        g_fill[0][t] = 0; g_fill[1][t] = 0;
    }
    if (t == 0) { g_ntiles[0] = 0; g_ntiles[1] = 0; }
}

// ---------------- routing: one warp per token (unchanged, verified) ----------------
__global__ void routing_kernel(const float* __restrict__ h,
                               const float* __restrict__ Wg,
                               const float* __restrict__ bg,
                               const float* __restrict__ Wloc,
                               float* __restrict__ o_eid,    // may be null
                               float* __restrict__ o_gate,   // may be null
                               float* __restrict__ o_grp,    // may be null
                               int n)
{
    int warp = (blockIdx.x * blockDim.x + threadIdx.x) >> 5;
    int lane = threadIdx.x & 31;
    if (warp >= n) return;

    const float* hrow = h + (size_t)warp * DDIM;

    float hv[32];
#pragma unroll
    for (int i = 0; i < 32; i++) hv[i] = hrow[i * 32 + lane];

    // ---- stage 1: group scores (G=8) ----
    float sg[GGRP];
#pragma unroll
    for (int g = 0; g < GGRP; g++) sg[g] = 0.f;
#pragma unroll
    for (int i = 0; i < 32; i++) {
        int d = i * 32 + lane;
        const float4* wp = (const float4*)(Wg + (size_t)d * GGRP);
        float4 wa = wp[0], wb = wp[1];
        float x = hv[i];
        sg[0] += x * wa.x; sg[1] += x * wa.y; sg[2] += x * wa.z; sg[3] += x * wa.w;
        sg[4] += x * wb.x; sg[5] += x * wb.y; sg[6] += x * wb.z; sg[7] += x * wb.w;
    }
#pragma unroll
    for (int g = 0; g < GGRP; g++) {
#pragma unroll
        for (int off = 16; off > 0; off >>= 1)
            sg[g] += __shfl_xor_sync(0xFFFFFFFFu, sg[g], off);
        sg[g] += bg[g];
    }
    int gi = 0; float best = sg[0];
#pragma unroll
    for (int g = 1; g < GGRP; g++) if (sg[g] > best) { best = sg[g]; gi = g; }

    // ---- stage 2: local scores for selected group (M=8) ----
    float sl[MLOC];
#pragma unroll
    for (int m = 0; m < MLOC; m++) sl[m] = 0.f;
    const float* wl = Wloc + (size_t)gi * DDIM * MLOC;
#pragma unroll
    for (int i = 0; i < 32; i++) {
        int d = i * 32 + lane;
        const float4* wp = (const float4*)(wl + (size_t)d * MLOC);
        float4 wa = wp[0], wb = wp[1];
        float x = hv[i];
        sl[0] += x * wa.x; sl[1] += x * wa.y; sl[2] += x * wa.z; sl[3] += x * wa.w;
        sl[4] += x * wb.x; sl[5] += x * wb.y; sl[6] += x * wb.z; sl[7] += x * wb.w;
    }
#pragma unroll
    for (int m = 0; m < MLOC; m++) {
#pragma unroll
        for (int off = 16; off > 0; off >>= 1)
            sl[m] += __shfl_xor_sync(0xFFFFFFFFu, sl[m], off);
    }
    int m1 = 0; float v1 = sl[0];
#pragma unroll
    for (int m = 1; m < MLOC; m++) if (sl[m] > v1) { v1 = sl[m]; m1 = m; }
    int m2 = -1; float v2 = -INFINITY;
#pragma unroll
    for (int m = 0; m < MLOC; m++) if (m != m1 && sl[m] > v2) { v2 = sl[m]; m2 = m; }

    float e2 = expf(v2 - v1);
    float inv = 1.0f / (1.0f + e2);
    float gate0 = inv;
    float gate1 = e2 * inv;

    int eid0 = gi * MLOC + m1;
    int eid1 = gi * MLOC + m2;

    if (lane == 0) {
        g_eid[2 * warp + 0] = eid0;
        g_eid[2 * warp + 1] = eid1;
        g_gate2[2 * warp + 0] = gate0;
        g_gate2[2 * warp + 1] = gate1;
        atomicAdd(&g_cnt[0][eid0], 1);
        atomicAdd(&g_cnt[1][eid1], 1);
        if (o_eid)  { o_eid[2 * warp + 0] = (float)eid0; o_eid[2 * warp + 1] = (float)eid1; }
        if (o_gate) { o_gate[2 * warp + 0] = gate0;      o_gate[2 * warp + 1] = gate1; }
        if (o_grp)  { o_grp[warp] = (float)gi; }
    }
}

// ---------------- prefix sums + tile lists (tiny; single thread) ----------------
__global__ void prefix_kernel() {
    if (threadIdx.x != 0 || blockIdx.x != 0) return;
#pragma unroll
    for (int s = 0; s < 2; s++) {
        int acc = 0, nt = 0;
        for (int e = 0; e < EEXP; e++) {
            g_off[s][e] = acc;
            int c = g_cnt[s][e];
            acc += c;
            int t = (c + TILE_T - 1) / TILE_T;
            for (int i = 0; i < t && nt < MAX_TILES; i++)
                g_tiles[s][nt++] = (e << 16) | i;
        }
        g_ntiles[s] = nt;
    }
}

// ---------------- scatter tokens into per-expert, per-slot buckets ----------------
__global__ void scatter_kernel(int n) {
    int t = blockIdx.x * blockDim.x + threadIdx.x;
    if (t >= n) return;
#pragma unroll
    for (int j = 0; j < 2; j++) {
        int e = g_eid[2 * t + j];
        int p = g_off[j][e] + atomicAdd(&g_fill[j][e], 1);
        g_tok[j][p] = t;
        g_tg[j][p]  = g_gate2[2 * t + j];
    }
}

// ---------------- expert compute: one tile = (slot, expert, 32 tokens) ----------------
// Both slots in ONE launch (slot0 -> out, slot1 -> g_extra); no atomics.
// Phase 1: A = gate * relu(H @ W1[e])  (32 x 64), ping-pong k-tiles of 32, reg-prefetch.
// Phase 2: O = A @ W2[e]               (32 x 1024), 64-col tiles, reg-prefetch.
// Thread map: tt = tid&15 -> tokens {2tt, 2tt+1}; rg = tid>>4 -> 4 cols {4rg..4rg+3}.
__global__ void __launch_bounds__(256)
expert_kernel(const float* __restrict__ h,
              const float* __restrict__ W1,
              const float* __restrict__ W2,
              float* __restrict__ out)
{
    __shared__ __align__(16) float s_ht[2][32][34];  // H^T ping-pong: [buf][k][token]
    __shared__ __align__(16) float s_w[2 * 32 * 64]; // W1 ping-pong (2x 32x64) / W2 single 64x64
    __shared__ __align__(16) float s_at[64][34];     // A^T: [r][token]
    __shared__ int   tok_s[TILE_T];
    __shared__ float gsc[TILE_T];

    int tid = threadIdx.x;
    int tt = tid & 15, rg = tid >> 4;
    int t0 = 2 * tt, t1 = t0 + 1;
    int r0 = rg * 4;

    // fill index precompute
    int fh_t = (tid >> 5);           // + 8*i  -> token for H fill
    int fh_k = tid & 31;             // k within chunk
    int fw_r = tid >> 6;             // + 4*i  -> row for W fills (64-wide)
    int fw_c = tid & 63;

    int nt0 = g_ntiles[0];
    int ntt = nt0 + g_ntiles[1];

    for (int tile = blockIdx.x; tile < ntt; tile += gridDim.x) {
        int slot = (tile >= nt0) ? 1 : 0;
        int tloc = slot ? tile - nt0 : tile;
        int desc = g_tiles[slot][tloc];
        int e  = desc >> 16;
        int ti = desc & 0xFFFF;
        int cnt_e = g_cnt[slot][e];
        int base  = g_off[slot][e] + ti * TILE_T;
        int nv = cnt_e - ti * TILE_T;
        if (nv > TILE_T) nv = TILE_T;

        if (tid < TILE_T) {
            int rr = tid < nv ? tid : (nv - 1);   // clamp; invalid rows masked at store
            tok_s[tid] = g_tok[slot][base + rr];
            gsc[tid]   = g_tg[slot][base + rr];
        }
        __syncthreads();

        const float* W1e = W1 + (size_t)e * DDIM * RRANK;

        // token row pointers for this thread's H-fill lanes (tokens fh_t, fh_t+8, +16, +24)
        const float* hp0 = h + (size_t)tok_s[fh_t +  0] * DDIM + fh_k;
        const float* hp1 = h + (size_t)tok_s[fh_t +  8] * DDIM + fh_k;
        const float* hp2 = h + (size_t)tok_s[fh_t + 16] * DDIM + fh_k;
        const float* hp3 = h + (size_t)tok_s[fh_t + 24] * DDIM + fh_k;

        float hr[4], wr[8];
        // preload k-tile 0
        hr[0] = hp0[0]; hr[1] = hp1[0]; hr[2] = hp2[0]; hr[3] = hp3[0];
#pragma unroll
        for (int i = 0; i < 8; i++)
            wr[i] = W1e[(size_t)(fw_r + 4 * i) * RRANK + fw_c];
        // store buf 0
        s_ht[0][fh_k][fh_t +  0] = hr[0];
        s_ht[0][fh_k][fh_t +  8] = hr[1];
        s_ht[0][fh_k][fh_t + 16] = hr[2];
        s_ht[0][fh_k][fh_t + 24] = hr[3];
#pragma unroll
        for (int i = 0; i < 8; i++)
            s_w[(fw_r + 4 * i) * 64 + fw_c] = wr[i];
        __syncthreads();

        // ---------------- phase 1 ----------------
        float a0[4] = {0.f, 0.f, 0.f, 0.f};
        float a1[4] = {0.f, 0.f, 0.f, 0.f};

        for (int kt = 0; kt < DDIM / 32; kt++) {
            int b = kt & 1;
            if (kt < DDIM / 32 - 1) {
                int k0 = (kt + 1) * 32;
                hr[0] = hp0[k0]; hr[1] = hp1[k0]; hr[2] = hp2[k0]; hr[3] = hp3[k0];
#pragma unroll
                for (int i = 0; i < 8; i++)
                    wr[i] = W1e[(size_t)(k0 + fw_r + 4 * i) * RRANK + fw_c];
            }
            const float* wb = s_w + b * 2048;
#pragma unroll
            for (int kk = 0; kk < 32; kk++) {
                float2 hp = *(const float2*)&s_ht[b][kk][t0];
                float4 w  = *(const float4*)&wb[kk * 64 + r0];
                a0[0] += hp.x * w.x; a0[1] += hp.x * w.y; a0[2] += hp.x * w.z; a0[3] += hp.x * w.w;
                a1[0] += hp.y * w.x; a1[1] += hp.y * w.y; a1[2] += hp.y * w.z; a1[3] += hp.y * w.w;
            }
            if (kt < DDIM / 32 - 1) {
                int nb = 1 - b;
                s_ht[nb][fh_k][fh_t +  0] = hr[0];
                s_ht[nb][fh_k][fh_t +  8] = hr[1];
                s_ht[nb][fh_k][fh_t + 16] = hr[2];
                s_ht[nb][fh_k][fh_t + 24] = hr[3];
#pragma unroll
                for (int i = 0; i < 8; i++)
                    s_w[nb * 2048 + (fw_r + 4 * i) * 64 + fw_c] = wr[i];
            }
            __syncthreads();
        }

        // ---------------- A^T write + W2 tile-0 prefetch ----------------
        const float* W2e = W2 + (size_t)e * RRANK * DDIM;
        float wr2[16];
#pragma unroll
        for (int i = 0; i < 16; i++)
            wr2[i] = W2e[(size_t)(fw_r + 4 * i) * DDIM + fw_c];

        float gt0 = gsc[t0], gt1 = gsc[t1];
#pragma unroll
        for (int j = 0; j < 4; j++)
            *(float2*)&s_at[r0 + j][t0] =
                make_float2(fmaxf(a0[j], 0.f) * gt0, fmaxf(a1[j], 0.f) * gt1);

#pragma unroll
        for (int i = 0; i < 16; i++)
            s_w[(fw_r + 4 * i) * 64 + fw_c] = wr2[i];
        __syncthreads();   // s_at + W2 tile 0 visible

        // ---------------- phase 2 ----------------
        bool v0 = (t0 < nv), v1 = (t1 < nv);
        size_t ob0 = (size_t)tok_s[t0] * DDIM;
        size_t ob1 = (size_t)tok_s[t1] * DDIM;
        float* dst = slot ? g_extra : out;

        for (int ct = 0; ct < 16; ct++) {
            if (ct < 15) {
                int c0 = (ct + 1) * 64;
#pragma unroll
                for (int i = 0; i < 16; i++)
                    wr2[i] = W2e[(size_t)(fw_r + 4 * i) * DDIM + c0 + fw_c];
            }
            float o0[4] = {0.f, 0.f, 0.f, 0.f};
            float o1[4] = {0.f, 0.f, 0.f, 0.f};
#pragma unroll
            for (int r = 0; r < RRANK; r++) {
                float2 ap = *(const float2*)&s_at[r][t0];
                float4 w  = *(const float4*)&s_w[r * 64 + r0];
                o0[0] += ap.x * w.x; o0[1] += ap.x * w.y; o0[2] += ap.x * w.z; o0[3] += ap.x * w.w;
                o1[0] += ap.y * w.x; o1[1] += ap.y * w.y; o1[2] += ap.y * w.z; o1[3] += ap.y * w.w;
            }
            int c = ct * 64 + r0;
            if (v0) *(float4*)&dst[ob0 + c] = make_float4(o0[0], o0[1], o0[2], o0[3]);
            if (v1) *(float4*)&dst[ob1 + c] = make_float4(o1[0], o1[1], o1[2], o1[3]);
            __syncthreads();            // everyone done reading s_w (and, last iter, s_at/tok_s)
            if (ct < 15) {
#pragma unroll
                for (int i = 0; i < 16; i++)
                    s_w[(fw_r + 4 * i) * 64 + fw_c] = wr2[i];
                __syncthreads();
            }
        }
    }
}

// ---------------- merge: out += g_extra ----------------
__global__ void add_kernel(float* __restrict__ out, int n4) {
    int i = blockIdx.x * blockDim.x + threadIdx.x;
    int stride = gridDim.x * blockDim.x;
    const float4* ex = (const float4*)g_extra;
    float4* o = (float4*)out;
    for (; i < n4; i += stride) {
        float4 a = o[i], b = ex[i];
        a.x += b.x; a.y += b.y; a.z += b.z; a.w += b.w;
        o[i] = a;
    }
}

// ---------------- launch ----------------
extern "C" void kernel_launch(void* const* d_in, const int* in_sizes, int n_in,
                              void* d_out, int out_size)
{
    const float* h    = (const float*)d_in[0];
    const float* Wg   = (const float*)d_in[1];
    const float* bg   = (const float*)d_in[2];
    const float* Wloc = (const float*)d_in[3];
    const float* W1   = (const float*)d_in[4];
    const float* W2   = (const float*)d_in[5];

    int n = in_sizes[0] / DDIM;                 // 8192
    if (n > NTOK) n = NTOK;

    float* out = (float*)d_out;

    // Optional concatenated tail outputs: out(N*D), expert_ids(2N), gate(2N), group_idx(N)
    size_t need = (size_t)n * DDIM + 5 * (size_t)n;
    float* o_eid  = nullptr;
    float* o_gate = nullptr;
    float* o_grp  = nullptr;
    if ((size_t)out_size >= need) {
        o_eid  = out + (size_t)n * DDIM;
        o_gate = o_eid + 2 * (size_t)n;
        o_grp  = o_gate + 2 * (size_t)n;
    }

    init_kernel<<<1, 128>>>();
    routing_kernel<<<(n + 7) / 8, 256>>>(h, Wg, bg, Wloc, o_eid, o_gate, o_grp, n);
    prefix_kernel<<<1, 32>>>();
    scatter_kernel<<<(n + 255) / 256, 256>>>(n);
    // Both slots in one wave: slot0 tiles write `out`, slot1 tiles write g_extra
    expert_kernel<<<592, 256>>>(h, W1, W2, out);
    // out += g_extra
    add_kernel<<<1024, 256>>>(out, n * DDIM / 4);
}